// round 10
// baseline (speedup 1.0000x reference)
#include <cuda_runtime.h>
#include <cstdint>

// ParabolicPool2D: out[b,c,oh,ow] = max_{p,q in 0..2} f[b,c,2*oh+p,2*ow+q] + h[c,p,q]
// h[c,p,q] = a[p] + a[q]  with a[0]=a[2]=-t[c]/2, a[1]=0   (separable)
//
//   rowred[r,ow] = max( max(f[r,2ow], f[r,2ow+2]) + a, f[r,2ow+1] )
//   out[oh,ow]   = max( max(rowred[2oh], rowred[2oh+2]) + a, rowred[2oh+1] )
//
// Each thread owns 2 output columns (one float4 load per row). The 5th input
// element (col+4) is the NEIGHBOR LANE's v.x -> fetched via __shfl_down_sync
// instead of a scalar LDG (only tx==31 crosses the warp boundary and does a
// real predicated load; tx==63 never needs it).
// Vertical register sliding window: 2 new input rows per output row.
// R6->R7: revert to R5's pipeline config (bounds (64,16), unroll 4, deep
// prefetch — per-warp MLP beats occupancy here), halve LDG issue via shuffle.

#define B_  16
#define C_  128
#define H_  256
#define W_  256
#define OH_ 127
#define OW_ 127
#define SEGS 4
#define SEG_ROWS 32   // oh rows per segment (last segment has 31)

__global__ __launch_bounds__(64, 16)
void parabolic_pool_kernel(const float* __restrict__ f,
                           const float* __restrict__ t,
                           float* __restrict__ out)
{
    const int tx    = threadIdx.x;        // 0..63, owns output cols 2*tx, 2*tx+1
    const int plane = blockIdx.x;         // b*C + c
    const int seg   = blockIdx.y;         // oh segment

    const int c = plane & (C_ - 1);
    const float a = -0.5f * __ldg(&t[c]);

    const float* fp = f + (size_t)plane * (H_ * W_);
    float*       op = out + (size_t)plane * (OH_ * OW_);

    const int col  = tx * 4;              // 16B-aligned input column base
    const bool has2   = (tx < 63);        // second output column valid
    const bool edge31 = (tx == 31);       // needs a real cross-warp load

    const int oh0 = seg * SEG_ROWS;
    const int nh  = min(SEG_ROWS, OH_ - oh0);

    // ---- prime: row-reduce input row 2*oh0 ----
    const float* row = fp + (2 * oh0) * W_ + col;
    float4 v  = *reinterpret_cast<const float4*>(row);
    float  v4 = __shfl_down_sync(0xffffffffu, v.x, 1);
    if (edge31) v4 = row[4];

    float ra0 = fmaxf(fmaxf(v.x, v.z) + a, v.y);
    float ra1 = fmaxf(fmaxf(v.z, v4)  + a, v.w);

    // ---- prefetch rows for iteration 0 ----
    const float* rc = row + 2 * W_;
    float4 vb  = *reinterpret_cast<const float4*>(row + W_);
    float4 vc  = *reinterpret_cast<const float4*>(rc);
    float  vb4 = __shfl_down_sync(0xffffffffu, vb.x, 1);
    float  vc4 = __shfl_down_sync(0xffffffffu, vc.x, 1);
    if (edge31) { vb4 = (row + W_)[4]; vc4 = rc[4]; }

    float* orow = op + oh0 * OW_ + 2 * tx;

    #pragma unroll 4
    for (int i = 0; i < nh; ++i) {
        // ---- prefetch rows for iteration i+1 (pointer-clamped on last iter:
        // loads/shuffles stay unconditional & uniform; values dead past end) ----
        const bool more = (i + 1 < nh);
        const float* nrb = more ? (rc + W_)     : rc;
        const float* nrc = more ? (rc + 2 * W_) : rc;
        float4 nb  = *reinterpret_cast<const float4*>(nrb);
        float4 nc  = *reinterpret_cast<const float4*>(nrc);
        float  nb4 = __shfl_down_sync(0xffffffffu, nb.x, 1);
        float  nc4 = __shfl_down_sync(0xffffffffu, nc.x, 1);
        if (edge31) { nb4 = nrb[4]; nc4 = nrc[4]; }

        // ---- compute with current pair ----
        float rb0 = fmaxf(fmaxf(vb.x, vb.z) + a, vb.y);
        float rb1 = fmaxf(fmaxf(vb.z, vb4)  + a, vb.w);
        float rc0 = fmaxf(fmaxf(vc.x, vc.z) + a, vc.y);
        float rc1 = fmaxf(fmaxf(vc.z, vc4)  + a, vc.w);

        float o0 = fmaxf(fmaxf(ra0, rc0) + a, rb0);
        float o1 = fmaxf(fmaxf(ra1, rc1) + a, rb1);

        orow[0] = o0;
        if (has2) orow[1] = o1;
        orow += OW_;

        // ---- slide window ----
        ra0 = rc0;
        ra1 = rc1;
        vb = nb;  vc = nc;  vb4 = nb4;  vc4 = nc4;
        rc = nrc;
    }
}

extern "C" void kernel_launch(void* const* d_in, const int* in_sizes, int n_in,
                              void* d_out, int out_size)
{
    // Identify inputs by element count (robust to metadata ordering):
    // f: 16*128*256*256 = 134217728, t: 128
    const float* f = nullptr;
    const float* t = nullptr;
    for (int i = 0; i < n_in; ++i) {
        if (in_sizes[i] == B_ * C_ * H_ * W_) f = (const float*)d_in[i];
        else if (in_sizes[i] == C_)           t = (const float*)d_in[i];
    }
    float* out = (float*)d_out;

    dim3 grid(B_ * C_, SEGS);
    parabolic_pool_kernel<<<grid, 64>>>(f, t, out);
}

// round 15
// speedup vs baseline: 1.0193x; 1.0193x over previous
#include <cuda_runtime.h>
#include <cstdint>

// ParabolicPool2D: out[b,c,oh,ow] = max_{p,q in 0..2} f[b,c,2*oh+p,2*ow+q] + h[c,p,q]
// h[c,p,q] = a[p] + a[q]  with a[0]=a[2]=-t[c]/2, a[1]=0   (separable)
//
//   rowred[r,ow] = max( max(f[r,2ow], f[r,2ow+2]) + a, f[r,2ow+1] )
//   out[oh,ow]   = max( max(rowred[2oh], rowred[2oh+2]) + a, rowred[2oh+1] )
//
// Each thread owns 2 output columns (one float4 + one L1-hit scalar per row).
// Vertical register sliding window: 2 new input rows per output row.
// Structure is the proven R5 optimum: bounds (64,16), unroll 4, 1-iter-ahead
// prefetch with clamped pointers (regs 64, ~46% occ — per-warp MLP > occ here).
// R10->R11: add streaming cache hints — input is read-once (__ldcs), output is
// write-once (__stcs) — to free L2 ways / retire lines earlier at the LTS.

#define B_  16
#define C_  128
#define H_  256
#define W_  256
#define OH_ 127
#define OW_ 127
#define SEGS 4
#define SEG_ROWS 32   // oh rows per segment (last segment has 31)

__device__ __forceinline__ float4 ld_cs4(const float* p) {
    return __ldcs(reinterpret_cast<const float4*>(p));
}

__global__ __launch_bounds__(64, 16)
void parabolic_pool_kernel(const float* __restrict__ f,
                           const float* __restrict__ t,
                           float* __restrict__ out)
{
    const int tx    = threadIdx.x;        // 0..63, owns output cols 2*tx, 2*tx+1
    const int plane = blockIdx.x;         // b*C + c
    const int seg   = blockIdx.y;         // oh segment

    const int c = plane & (C_ - 1);
    const float a = -0.5f * __ldg(&t[c]);

    const float* fp = f + (size_t)plane * (H_ * W_);
    float*       op = out + (size_t)plane * (OH_ * OW_);

    const int col  = tx * 4;              // 16B-aligned input column base
    const bool has2 = (tx < 63);          // second output column valid

    const int oh0 = seg * SEG_ROWS;
    const int nh  = min(SEG_ROWS, OH_ - oh0);

    // ---- prime: row-reduce input row 2*oh0 ----
    const float* row = fp + (2 * oh0) * W_ + col;
    float4 v  = ld_cs4(row);
    float  v4 = has2 ? row[4] : 0.0f;     // L1-hit (same/neighbor line)

    float ra0 = fmaxf(fmaxf(v.x, v.z) + a, v.y);
    float ra1 = fmaxf(fmaxf(v.z, v4)  + a, v.w);

    // ---- prefetch rows for iteration 0 ----
    const float* rc = row + 2 * W_;
    float4 vb  = ld_cs4(row + W_);
    float4 vc  = ld_cs4(rc);
    float  vb4 = has2 ? (row + W_)[4] : 0.0f;
    float  vc4 = has2 ? rc[4] : 0.0f;

    float* orow = op + oh0 * OW_ + 2 * tx;

    #pragma unroll 4
    for (int i = 0; i < nh; ++i) {
        // ---- prefetch rows for iteration i+1 (pointer-clamped on last iter:
        // loads stay unconditional & uniform; values dead past end) ----
        const bool more = (i + 1 < nh);
        const float* nrb = more ? (rc + W_)     : rc;
        const float* nrc = more ? (rc + 2 * W_) : rc;
        float4 nb  = ld_cs4(nrb);
        float4 nc  = ld_cs4(nrc);
        float  nb4 = has2 ? nrb[4] : 0.0f;
        float  nc4 = has2 ? nrc[4] : 0.0f;

        // ---- compute with current pair ----
        float rb0 = fmaxf(fmaxf(vb.x, vb.z) + a, vb.y);
        float rb1 = fmaxf(fmaxf(vb.z, vb4)  + a, vb.w);
        float rc0 = fmaxf(fmaxf(vc.x, vc.z) + a, vc.y);
        float rc1 = fmaxf(fmaxf(vc.z, vc4)  + a, vc.w);

        float o0 = fmaxf(fmaxf(ra0, rc0) + a, rb0);
        float o1 = fmaxf(fmaxf(ra1, rc1) + a, rb1);

        __stcs(&orow[0], o0);
        if (has2) __stcs(&orow[1], o1);
        orow += OW_;

        // ---- slide window ----
        ra0 = rc0;
        ra1 = rc1;
        vb = nb;  vc = nc;  vb4 = nb4;  vc4 = nc4;
        rc = nrc;
    }
}

extern "C" void kernel_launch(void* const* d_in, const int* in_sizes, int n_in,
                              void* d_out, int out_size)
{
    // Identify inputs by element count (robust to metadata ordering):
    // f: 16*128*256*256 = 134217728, t: 128
    const float* f = nullptr;
    const float* t = nullptr;
    for (int i = 0; i < n_in; ++i) {
        if (in_sizes[i] == B_ * C_ * H_ * W_) f = (const float*)d_in[i];
        else if (in_sizes[i] == C_)           t = (const float*)d_in[i];
    }
    float* out = (float*)d_out;

    dim3 grid(B_ * C_, SEGS);
    parabolic_pool_kernel<<<grid, 64>>>(f, t, out);
}